// round 2
// baseline (speedup 1.0000x reference)
#include <cuda_runtime.h>

#define HH 96
#define WW 96
#define CC 256
#define NP (HH*WW)          // 9216 pixels per image
#define NB 2
#define HP 98
#define PADP (HP*HP)        // 9604 padded pixels
#define M6 1536
#define NTOT 18432.0f       // NB*NP

// ---------------- static scratch (no runtime allocation) ----------------
__device__ float g_xTp[(size_t)NB*PADP*CC];     // padded NHWC x, ~19.7 MB
__device__ float g_w[(size_t)NB*NP*48];         // guidance -> softmaxed weights (45 used, pad 48)
__device__ float g_Wt[(size_t)M6*CC];           // transposed W_scale: Wt[m'][c]
__device__ float g_Z[(size_t)NB*NP*M6];         // Z = per-block 1x1 GEMM of x, ~113 MB
__device__ float g_y[(size_t)NB*NP*CC];         // pre-BN output, NHWC
__device__ float g_stats[512];                  // [0:256) sum, [256:512) sumsq
__device__ float g_scale[CC];
__device__ float g_shift[CC];

// ---------------- init: zero padded buffer + stats ----------------
__global__ void k_init() {
    size_t total = (size_t)NB*PADP*CC;
    size_t stride = (size_t)gridDim.x * blockDim.x;
    for (size_t i = (size_t)blockIdx.x*blockDim.x + threadIdx.x; i < total; i += stride)
        g_xTp[i] = 0.f;
    size_t t0 = (size_t)blockIdx.x*blockDim.x + threadIdx.x;
    if (t0 < 512) g_stats[t0] = 0.f;
}

// ---------------- NCHW -> padded NHWC transpose ----------------
__global__ void k_pad_transpose(const float* __restrict__ x) {
    __shared__ float tile[32][33];
    int n  = blockIdx.z >> 3;
    int c0 = (blockIdx.z & 7) * 32;
    int y  = blockIdx.y;
    int x0 = blockIdx.x * 32;
    int tx = threadIdx.x, ty = threadIdx.y;
#pragma unroll
    for (int i = 0; i < 4; i++) {
        int c = c0 + ty + i*8;
        tile[ty + i*8][tx] = x[(((size_t)n*CC + c)*HH + y)*WW + x0 + tx];
    }
    __syncthreads();
#pragma unroll
    for (int i = 0; i < 4; i++) {
        int xl = ty + i*8;            // local x (pixel)
        int c  = c0 + tx;             // channel (coalesced)
        g_xTp[((size_t)n*PADP + (size_t)(y+1)*HP + (x0 + xl + 1))*CC + c] = tile[tx][xl];
    }
}

// ---------------- transpose W_scale: Wt[j*256+o][c] = Ws[o][j*256+c] ----------------
__global__ void k_wtrans(const float* __restrict__ ws) {
    int i = blockIdx.x*256 + threadIdx.x;    // over M6*CC
    int mp = i >> 8;                          // m' = j*256 + o
    int c  = i & 255;
    int o  = mp & 255, j = mp >> 8;
    g_Wt[i] = ws[(size_t)o*M6 + j*256 + c];
}

// ---------------- guidance conv as 9 shifted GEMMs: tile 128px x 48oc ----------------
__global__ __launch_bounds__(256, 2) void k_guidance(const float* __restrict__ wcat) {
    __shared__ float As[8][128];
    __shared__ float Bs[8][48];
    int n  = blockIdx.y;
    int pb = blockIdx.x * 128;
    int tid = threadIdx.x;

    // A-load mapping: each thread loads one float4 (128 rows x 8 k)
    int lm  = tid >> 1;
    int lk4 = (tid & 1) * 4;
    int p_l = pb + lm;
    int pyl = p_l / WW, pxl = p_l % WW;

    // compute mapping: 32 row-groups x 8 col-groups; 4 rows x 6 cols each
    int tx = tid & 31, ty = tid >> 5;

    float acc[4][6];
#pragma unroll
    for (int i = 0; i < 4; i++)
#pragma unroll
        for (int j = 0; j < 6; j++) acc[i][j] = 0.f;

    for (int tap = 0; tap < 9; ++tap) {
        int dy = tap/3 - 1, dx = tap%3 - 1;
        const float* arow = g_xTp + ((size_t)n*PADP + (size_t)(pyl+1+dy)*HP + (pxl+1+dx))*CC;
        for (int c0 = 0; c0 < 256; c0 += 8) {
            float4 av = *(const float4*)(arow + c0 + lk4);
            As[lk4+0][lm] = av.x; As[lk4+1][lm] = av.y;
            As[lk4+2][lm] = av.z; As[lk4+3][lm] = av.w;
            for (int q = tid; q < 8*48; q += 256) {
                int kc = q & 7, oc = q >> 3;
                Bs[kc][oc] = (oc < 45) ? wcat[((size_t)(oc*256 + c0 + kc))*9 + tap] : 0.f;
            }
            __syncthreads();
#pragma unroll
            for (int kc = 0; kc < 8; kc++) {
                float4 a = *(const float4*)&As[kc][tx*4];
                float bq[6];
#pragma unroll
                for (int j = 0; j < 6; j++) bq[j] = Bs[kc][ty*6 + j];
#pragma unroll
                for (int j = 0; j < 6; j++) {
                    acc[0][j] += a.x * bq[j];
                    acc[1][j] += a.y * bq[j];
                    acc[2][j] += a.z * bq[j];
                    acc[3][j] += a.w * bq[j];
                }
            }
            __syncthreads();
        }
    }
#pragma unroll
    for (int i = 0; i < 4; i++) {
        size_t row = ((size_t)n*NP + pb + tx*4 + i)*48;
#pragma unroll
        for (int j = 0; j < 6; j++) {
            int oc = ty*6 + j;
            if (oc < 45) g_w[row + oc] = acc[i][j];
        }
    }
}

// ---------------- softmax over each 9-channel group ----------------
__global__ void k_softmax() {
    int i = blockIdx.x*256 + threadIdx.x;     // over NB*NP*5
    if (i >= NB*NP*5) return;
    int br  = i % 5;
    int np_ = i / 5;
    float* row = g_w + (size_t)np_*48 + 9*br;
    float v[9], m = -1e30f;
#pragma unroll
    for (int k = 0; k < 9; k++) { v[k] = row[k]; m = fmaxf(m, v[k]); }
    float s = 0.f;
#pragma unroll
    for (int k = 0; k < 9; k++) { v[k] = __expf(v[k] - m); s += v[k]; }
    float inv = 1.f / s;
#pragma unroll
    for (int k = 0; k < 9; k++) row[k] = v[k] * inv;
}

// ---------------- Z GEMM: (18432 x 256) @ (256 x 1536), 128x128x8 tiles ----------------
__global__ __launch_bounds__(256, 2) void k_zgemm() {
    __shared__ float As[8][128];
    __shared__ float Bs[8][128];
    int n  = blockIdx.z;
    int pb = blockIdx.x * 128;
    int nb = blockIdx.y * 128;
    int tid = threadIdx.x;

    int lm  = tid >> 1;
    int lk4 = (tid & 1) * 4;
    int p_l = pb + lm;
    int pyl = p_l / WW, pxl = p_l % WW;
    const float* arow = g_xTp + ((size_t)n*PADP + (size_t)(pyl+1)*HP + (pxl+1))*CC;
    const float* brow = g_Wt + (size_t)(nb + lm)*CC;

    int tx = tid & 15, ty = tid >> 4;

    float acc[8][8];
#pragma unroll
    for (int i = 0; i < 8; i++)
#pragma unroll
        for (int j = 0; j < 8; j++) acc[i][j] = 0.f;

    for (int c0 = 0; c0 < 256; c0 += 8) {
        float4 av = *(const float4*)(arow + c0 + lk4);
        float4 bv = *(const float4*)(brow + c0 + lk4);
        As[lk4+0][lm] = av.x; As[lk4+1][lm] = av.y;
        As[lk4+2][lm] = av.z; As[lk4+3][lm] = av.w;
        Bs[lk4+0][lm] = bv.x; Bs[lk4+1][lm] = bv.y;
        Bs[lk4+2][lm] = bv.z; Bs[lk4+3][lm] = bv.w;
        __syncthreads();
#pragma unroll
        for (int kc = 0; kc < 8; kc++) {
            float4 a0 = *(const float4*)&As[kc][tx*4];
            float4 a1 = *(const float4*)&As[kc][64 + tx*4];
            float4 b0 = *(const float4*)&Bs[kc][ty*4];
            float4 b1 = *(const float4*)&Bs[kc][64 + ty*4];
            float a[8] = {a0.x,a0.y,a0.z,a0.w,a1.x,a1.y,a1.z,a1.w};
            float b[8] = {b0.x,b0.y,b0.z,b0.w,b1.x,b1.y,b1.z,b1.w};
#pragma unroll
            for (int i = 0; i < 8; i++)
#pragma unroll
                for (int j = 0; j < 8; j++) acc[i][j] += a[i]*b[j];
        }
        __syncthreads();
    }
#pragma unroll
    for (int i = 0; i < 8; i++) {
        int pr = pb + ((i < 4) ? (tx*4 + i) : (64 + tx*4 + i - 4));
        float* crow = g_Z + ((size_t)n*NP + pr)*M6 + nb;
        *(float4*)(crow + ty*4)      = make_float4(acc[i][0], acc[i][1], acc[i][2], acc[i][3]);
        *(float4*)(crow + 64 + ty*4) = make_float4(acc[i][4], acc[i][5], acc[i][6], acc[i][7]);
    }
}

// ---------------- gather: y = z0 + sum_j sum_k w_jk * shift(z_j), warp per pixel ----------------
__global__ __launch_bounds__(256) void k_gather() {
    __shared__ float wsh[8][48];
    int warp = threadIdx.x >> 5, lane = threadIdx.x & 31;
    int P = blockIdx.x*8 + warp;                // global (n,p)
    int n = P / NP, p = P % NP;
    int py = p / WW, px = p % WW;

    const float* wrow = g_w + (size_t)P*48;
    if (lane < 45) wsh[warp][lane] = wrow[lane];
    if (lane < 13) wsh[warp][32 + lane] = wrow[32 + lane];
    __syncwarp();

    const float* z0 = g_Z + (size_t)P*M6 + lane*8;
    float4 A0 = *(const float4*)z0;
    float4 A1 = *(const float4*)(z0 + 4);

    const int DS[5] = {1, 6, 12, 24, 36};
#pragma unroll
    for (int br = 0; br < 5; ++br) {
        int d = DS[br];
#pragma unroll
        for (int k = 0; k < 9; k++) {
            int dy = (k/3 - 1)*d, dx = (k%3 - 1)*d;
            int ny = py + dy, nx = px + dx;
            if ((unsigned)ny < HH && (unsigned)nx < WW) {
                float w = wsh[warp][br*9 + k];
                const float* zr = g_Z + ((size_t)n*NP + ny*WW + nx)*M6 + (br+1)*256 + lane*8;
                float4 v0 = *(const float4*)zr;
                float4 v1 = *(const float4*)(zr + 4);
                A0.x += w*v0.x; A0.y += w*v0.y; A0.z += w*v0.z; A0.w += w*v0.w;
                A1.x += w*v1.x; A1.y += w*v1.y; A1.z += w*v1.z; A1.w += w*v1.w;
            }
        }
    }
    float* yr = g_y + (size_t)P*CC + lane*8;
    *(float4*)yr       = A0;
    *((float4*)yr + 1) = A1;
}

// ---------------- BN stats ----------------
__global__ void k_stats() {
    int t = threadIdx.x;                   // channel
    size_t row0 = (size_t)blockIdx.x * 18; // 1024 blocks * 18 = 18432 rows
    float s = 0.f, s2 = 0.f;
    for (int r = 0; r < 18; r++) {
        float v = g_y[(row0 + r)*CC + t];
        s += v; s2 += v*v;
    }
    atomicAdd(&g_stats[t], s);
    atomicAdd(&g_stats[256 + t], s2);
}

__global__ void k_finalize(const float* __restrict__ gamma, const float* __restrict__ beta) {
    int t = threadIdx.x;
    float mean = g_stats[t] / NTOT;
    float var  = g_stats[256 + t] / NTOT - mean*mean;
    float rstd = rsqrtf(var + 1e-5f);
    float sc = gamma[t] * rstd;
    g_scale[t] = sc;
    g_shift[t] = beta[t] - mean*sc;
}

// ---------------- affine + NHWC -> NCHW transpose ----------------
__global__ void k_norm(float* __restrict__ out) {
    __shared__ float tile[32][33];
    int n  = blockIdx.z;
    int o0 = blockIdx.y * 32;
    int p0 = blockIdx.x * 32;
    int tx = threadIdx.x, ty = threadIdx.y;
#pragma unroll
    for (int i = 0; i < 4; i++) {
        int pl = ty + i*8;
        int oo = o0 + tx;
        tile[pl][tx] = g_y[((size_t)n*NP + p0 + pl)*CC + oo] * g_scale[oo] + g_shift[oo];
    }
    __syncthreads();
#pragma unroll
    for (int i = 0; i < 4; i++) {
        int ol = ty + i*8;
        out[((size_t)(n*CC + o0 + ol))*NP + p0 + tx] = tile[tx][ol];
    }
}

// ---------------- launch ----------------
extern "C" void kernel_launch(void* const* d_in, const int* in_sizes, int n_in,
                              void* d_out, int out_size) {
    const float* x     = (const float*)d_in[0];
    const float* wcat  = (const float*)d_in[1];
    const float* wscl  = (const float*)d_in[2];
    const float* gamma = (const float*)d_in[3];
    const float* beta  = (const float*)d_in[4];
    float* out = (float*)d_out;

    k_init<<<1200, 1024>>>();
    {
        dim3 g(3, 96, NB*8), b(32, 8);
        k_pad_transpose<<<g, b>>>(x);
    }
    k_wtrans<<<(M6*CC)/256, 256>>>(wscl);
    {
        dim3 g(NP/128, NB);
        k_guidance<<<g, 256>>>(wcat);
    }
    k_softmax<<<(NB*NP*5 + 255)/256, 256>>>();
    {
        dim3 g(NP/128, M6/128, NB);
        k_zgemm<<<g, 256>>>();
    }
    k_gather<<<(NB*NP)/8, 256>>>();
    k_stats<<<1024, 256>>>();
    k_finalize<<<1, 256>>>(gamma, beta);
    {
        dim3 g(NP/32, CC/32, NB), b(32, 8);
        k_norm<<<g, b>>>(out);
    }
}

// round 5
// speedup vs baseline: 2.5000x; 2.5000x over previous
#include <cuda_runtime.h>
#include <cuda_bf16.h>
#include <cstdint>

#define HH 96
#define WW 96
#define CC 256
#define NP (HH*WW)          // 9216 pixels per image
#define NB 2
#define HP 98
#define PADP (HP*HP)        // 9604 padded pixels
#define NOUT 2048           // GEMM N: 1536 (Z) + 432 (guidance taps) + 80 pad
#define NGUID 1536
#define NTOT 18432.0f

// ---------------- static scratch ----------------
__device__ __nv_bfloat16 g_Ahi[(size_t)NB*PADP*CC];   // padded NHWC x, hi bf16
__device__ __nv_bfloat16 g_Alo[(size_t)NB*PADP*CC];   // residual lo bf16
__device__ __nv_bfloat16 g_Bhi[(size_t)NOUT*CC];      // [W_t ; tap weights] hi
__device__ __nv_bfloat16 g_Blo[(size_t)NOUT*CC];      // lo
__device__ float g_Z[(size_t)NB*NP*NOUT];             // GEMM output (Z + tap partials)
__device__ float g_w[(size_t)NB*NP*48];               // guidance -> softmax weights
__device__ float g_y[(size_t)NB*NP*CC];               // pre-BN output, NHWC
__device__ float g_stats[512];
__device__ float g_scale[CC];
__device__ float g_shift[CC];

// ================= helpers =================
__device__ __forceinline__ uint32_t smem_u32(const void* p) {
    uint32_t a;
    asm("{ .reg .u64 t; cvta.to.shared.u64 t, %1; cvt.u32.u64 %0, t; }" : "=r"(a) : "l"(p));
    return a;
}
#define SWZ128(o) ((o) ^ (((o) >> 3) & 0x70))

__device__ __forceinline__ void ldsm_x4(uint32_t& r0, uint32_t& r1, uint32_t& r2, uint32_t& r3,
                                        uint32_t addr) {
    asm volatile("ldmatrix.sync.aligned.m8n8.x4.shared.b16 {%0,%1,%2,%3}, [%4];"
                 : "=r"(r0), "=r"(r1), "=r"(r2), "=r"(r3) : "r"(addr));
}
__device__ __forceinline__ void mma16816(float* d, const uint32_t* a, const uint32_t* b) {
    asm volatile("mma.sync.aligned.m16n8k16.row.col.f32.bf16.bf16.f32 "
                 "{%0,%1,%2,%3}, {%4,%5,%6,%7}, {%8,%9}, {%0,%1,%2,%3};"
                 : "+f"(d[0]), "+f"(d[1]), "+f"(d[2]), "+f"(d[3])
                 : "r"(a[0]), "r"(a[1]), "r"(a[2]), "r"(a[3]), "r"(b[0]), "r"(b[1]));
}

// ---------------- init: zero bf16 padded inputs + stats ----------------
__global__ void k_init() {
    size_t total = ((size_t)NB*PADP*CC) / 8;   // uint4 = 8 bf16
    size_t stride = (size_t)gridDim.x * blockDim.x;
    uint4 z = make_uint4(0, 0, 0, 0);
    for (size_t i = (size_t)blockIdx.x*blockDim.x + threadIdx.x; i < total; i += stride) {
        ((uint4*)g_Ahi)[i] = z;
        ((uint4*)g_Alo)[i] = z;
    }
    size_t t0 = (size_t)blockIdx.x*blockDim.x + threadIdx.x;
    if (t0 < 512) g_stats[t0] = 0.f;
}

// ---------------- NCHW -> padded NHWC, split fp32 -> bf16 hi/lo ----------------
__global__ void k_pad_split(const float* __restrict__ x) {
    __shared__ float tile[32][33];
    int n  = blockIdx.z >> 3;
    int c0 = (blockIdx.z & 7) * 32;
    int y  = blockIdx.y;
    int x0 = blockIdx.x * 32;
    int tx = threadIdx.x, ty = threadIdx.y;
#pragma unroll
    for (int i = 0; i < 4; i++) {
        int c = c0 + ty + i*8;
        tile[ty + i*8][tx] = x[(((size_t)n*CC + c)*HH + y)*WW + x0 + tx];
    }
    __syncthreads();
#pragma unroll
    for (int i = 0; i < 4; i++) {
        int xl = ty + i*8;
        int c  = c0 + tx;
        float v = tile[tx][xl];
        __nv_bfloat16 h = __float2bfloat16(v);
        float lo = v - __bfloat162float(h);
        size_t idx = ((size_t)n*PADP + (size_t)(y+1)*HP + (x0 + xl + 1))*CC + c;
        g_Ahi[idx] = h;
        g_Alo[idx] = __float2bfloat16(lo);
    }
}

// ---------------- build B = [W_t ; tap weights], split hi/lo ----------------
__global__ void k_wsplit(const float* __restrict__ ws, const float* __restrict__ wcat) {
    int i = blockIdx.x*256 + threadIdx.x;   // over NOUT*CC
    int mp = i >> 8, c = i & 255;
    float v = 0.f;
    if (mp < NGUID) {
        int o = mp & 255, j = mp >> 8;
        v = ws[(size_t)o*NGUID + j*256 + c];
    } else if (mp < NGUID + 432) {
        int t = mp - NGUID, tap = t / 48, oc = t % 48;
        if (oc < 45) v = wcat[((size_t)(oc*256 + c))*9 + tap];
    }
    __nv_bfloat16 h = __float2bfloat16(v);
    g_Bhi[i] = h;
    g_Blo[i] = __float2bfloat16(v - __bfloat162float(h));
}

// ---------------- warp-MMA GEMM: 18432 x 2048 x 256, fp32 via bf16 3-way split ----------------
// SMEM: K-major tiles, 128 rows x 64 bf16 (128B rows, SW128 swizzle)
#define SM_AHI 0
#define SM_ALO 16384
#define SM_BHI 32768
#define SM_BLO 49152
#define SM_TOTAL 65536

__global__ __launch_bounds__(256, 2) void k_gemm() {
    extern __shared__ char smem[];
    uint32_t smemu = smem_u32(smem);
    int tid = threadIdx.x, wid = tid >> 5, lane = tid & 31;
    int n  = blockIdx.z;
    int pb = blockIdx.x * 128;
    int nb = blockIdx.y * 128;

    // ---- loader mapping: thread -> (row r, half); 64B per array per chunk ----
    int r = tid >> 1;
    int half = tid & 1;
    int p  = pb + r;
    int py = p / WW, px = p % WW;
    size_t aoff = ((size_t)n*PADP + (size_t)(py+1)*HP + (px+1))*CC + half*32;
    size_t boff = (size_t)(nb + r)*CC + half*32;
    uint32_t so[4];
#pragma unroll
    for (int i = 0; i < 4; i++) {
        uint32_t o = (uint32_t)(r*128 + half*64 + i*16);
        so[i] = SWZ128(o);
    }

    // ---- warp tile mapping: 4 warps over M (32 each), 2 over N (64 each) ----
    int wm = wid & 3, wn = wid >> 2;

    // ldmatrix lane addressing (swizzle: row%8 == lane&7 for both A and B)
    uint32_t xorv = (uint32_t)((lane & 7) << 4);
    // A: matrices {m0-7,k0-7},{m8-15,k0-7},{m0-7,k8-15},{m8-15,k8-15}
    int a_row0 = wm*32 + ((lane >> 3) & 1)*8 + (lane & 7);
    uint32_t a_colsel = (uint32_t)((lane >> 4) * 16);      // k-half
    // B: matrices {n0-7,k0-7},{n0-7,k8-15},{n8-15,k0-7},{n8-15,k8-15}
    int b_row0 = wn*64 + ((lane >> 4))*8 + (lane & 7);
    uint32_t b_colsel = (uint32_t)(((lane >> 3) & 1) * 16);

    uint32_t aBaseHi0 = smemu + SM_AHI + (uint32_t)(a_row0*128);
    uint32_t aBaseHi1 = aBaseHi0 + 16*128;
    uint32_t aBaseLo0 = aBaseHi0 + (SM_ALO - SM_AHI);
    uint32_t aBaseLo1 = aBaseHi1 + (SM_ALO - SM_AHI);
    uint32_t bBaseHi  = smemu + SM_BHI + (uint32_t)(b_row0*128);
    uint32_t bBaseLo  = bBaseHi + (SM_BLO - SM_BHI);

    float acc[2][8][4];
#pragma unroll
    for (int t = 0; t < 2; t++)
#pragma unroll
        for (int q = 0; q < 8; q++)
#pragma unroll
            for (int e = 0; e < 4; e++) acc[t][q][e] = 0.f;

    for (int kc = 0; kc < 4; kc++) {
        // ---- load 64 KB chunk ----
        const uint4* pah = (const uint4*)(g_Ahi + aoff + kc*64);
        const uint4* pal = (const uint4*)(g_Alo + aoff + kc*64);
        const uint4* pbh = (const uint4*)(g_Bhi + boff + kc*64);
        const uint4* pbl = (const uint4*)(g_Blo + boff + kc*64);
#pragma unroll
        for (int i = 0; i < 4; i++) {
            *(uint4*)(smem + SM_AHI + so[i]) = pah[i];
            *(uint4*)(smem + SM_ALO + so[i]) = pal[i];
            *(uint4*)(smem + SM_BHI + so[i]) = pbh[i];
            *(uint4*)(smem + SM_BLO + so[i]) = pbl[i];
        }
        __syncthreads();

#pragma unroll
        for (int ks = 0; ks < 4; ks++) {
            uint32_t aoffs = ((uint32_t)(ks*32) + a_colsel) ^ xorv;
            uint32_t boffs = ((uint32_t)(ks*32) + b_colsel) ^ xorv;

            uint32_t ah[2][4], al[2][4];
            ldsm_x4(ah[0][0], ah[0][1], ah[0][2], ah[0][3], aBaseHi0 + aoffs);
            ldsm_x4(ah[1][0], ah[1][1], ah[1][2], ah[1][3], aBaseHi1 + aoffs);
            ldsm_x4(al[0][0], al[0][1], al[0][2], al[0][3], aBaseLo0 + aoffs);
            ldsm_x4(al[1][0], al[1][1], al[1][2], al[1][3], aBaseLo1 + aoffs);

#pragma unroll
            for (int qp = 0; qp < 4; qp++) {
                uint32_t bh[4], bl[4];
                ldsm_x4(bh[0], bh[1], bh[2], bh[3], bBaseHi + (uint32_t)(qp*16*128) + boffs);
                ldsm_x4(bl[0], bl[1], bl[2], bl[3], bBaseLo + (uint32_t)(qp*16*128) + boffs);
                int q0 = qp*2, q1 = qp*2 + 1;
                // hi*hi
                mma16816(acc[0][q0], ah[0], bh + 0);
                mma16816(acc[1][q0], ah[1], bh + 0);
                mma16816(acc[0][q1], ah[0], bh + 2);
                mma16816(acc[1][q1], ah[1], bh + 2);
                // hi*lo
                mma16816(acc[0][q0], ah[0], bl + 0);
                mma16816(acc[1][q0], ah[1], bl + 0);
                mma16816(acc[0][q1], ah[0], bl + 2);
                mma16816(acc[1][q1], ah[1], bl + 2);
                // lo*hi
                mma16816(acc[0][q0], al[0], bh + 0);
                mma16816(acc[1][q0], al[1], bh + 0);
                mma16816(acc[0][q1], al[0], bh + 2);
                mma16816(acc[1][q1], al[1], bh + 2);
            }
        }
        __syncthreads();
    }

    // ---- epilogue: write fragments to g_Z ----
#pragma unroll
    for (int t = 0; t < 2; t++) {
        size_t row = (size_t)n*NP + pb + wm*32 + t*16 + (lane >> 2);
        float* zbase = g_Z + row*NOUT + nb + wn*64 + (lane & 3)*2;
#pragma unroll
        for (int q = 0; q < 8; q++) {
            *(float2*)(zbase + q*8)          = make_float2(acc[t][q][0], acc[t][q][1]);
            *(float2*)(zbase + q*8 + 8*NOUT) = make_float2(acc[t][q][2], acc[t][q][3]);
        }
    }
}

// ---------------- guidance = shifted sum of tap partials ----------------
__global__ void k_gsum() {
    int i = blockIdx.x*256 + threadIdx.x;
    if (i >= NB*NP*48) return;
    int oc = i % 48;
    int P  = i / 48;
    int n  = P / NP, p = P % NP;
    int py = p / WW, px = p % WW;
    float s = 0.f;
#pragma unroll
    for (int tap = 0; tap < 9; tap++) {
        int dy = tap/3 - 1, dx = tap%3 - 1;
        int qy = py + dy, qx = px + dx;
        if ((unsigned)qy < HH && (unsigned)qx < WW)
            s += g_Z[((size_t)n*NP + qy*WW + qx)*NOUT + NGUID + tap*48 + oc];
    }
    g_w[(size_t)P*48 + oc] = s;
}

// ---------------- softmax over each 9-channel group ----------------
__global__ void k_softmax() {
    int i = blockIdx.x*256 + threadIdx.x;
    if (i >= NB*NP*5) return;
    int br  = i % 5;
    int np_ = i / 5;
    float* row = g_w + (size_t)np_*48 + 9*br;
    float v[9], m = -1e30f;
#pragma unroll
    for (int k = 0; k < 9; k++) { v[k] = row[k]; m = fmaxf(m, v[k]); }
    float s = 0.f;
#pragma unroll
    for (int k = 0; k < 9; k++) { v[k] = __expf(v[k] - m); s += v[k]; }
    float inv = 1.f / s;
#pragma unroll
    for (int k = 0; k < 9; k++) row[k] = v[k] * inv;
}

// ---------------- gather: y = z0 + sum_br sum_k w * shift(z_br) ----------------
__global__ __launch_bounds__(256) void k_gather() {
    __shared__ float wsh[8][48];
    int warp = threadIdx.x >> 5, lane = threadIdx.x & 31;
    int P = blockIdx.x*8 + warp;
    int n = P / NP, p = P % NP;
    int py = p / WW, px = p % WW;

    const float* wrow = g_w + (size_t)P*48;
    if (lane < 45) wsh[warp][lane] = wrow[lane];
    if (lane < 13) wsh[warp][32 + lane] = wrow[32 + lane];
    __syncwarp();

    const float* z0 = g_Z + (size_t)P*NOUT + lane*8;
    float4 A0 = *(const float4*)z0;
    float4 A1 = *(const float4*)(z0 + 4);

    const int DS[5] = {1, 6, 12, 24, 36};
#pragma unroll
    for (int br = 0; br < 5; ++br) {
        int d = DS[br];
#pragma unroll
        for (int k = 0; k < 9; k++) {
            int dy = (k/3 - 1)*d, dx = (k%3 - 1)*d;
            int ny = py + dy, nx = px + dx;
            if ((unsigned)ny < HH && (unsigned)nx < WW) {
                float w = wsh[warp][br*9 + k];
                const float* zr = g_Z + ((size_t)n*NP + ny*WW + nx)*NOUT + (br+1)*256 + lane*8;
                float4 v0 = *(const float4*)zr;
                float4 v1 = *(const float4*)(zr + 4);
                A0.x += w*v0.x; A0.y += w*v0.y; A0.z += w*v0.z; A0.w += w*v0.w;
                A1.x += w*v1.x; A1.y += w*v1.y; A1.z += w*v1.z; A1.w += w*v1.w;
            }
        }
    }
    float* yr = g_y + (size_t)P*CC + lane*8;
    *(float4*)yr       = A0;
    *((float4*)yr + 1) = A1;
}

// ---------------- BN stats ----------------
__global__ void k_stats() {
    int t = threadIdx.x;
    size_t row0 = (size_t)blockIdx.x * 18;
    float s = 0.f, s2 = 0.f;
    for (int r = 0; r < 18; r++) {
        float v = g_y[(row0 + r)*CC + t];
        s += v; s2 += v*v;
    }
    atomicAdd(&g_stats[t], s);
    atomicAdd(&g_stats[256 + t], s2);
}

__global__ void k_finalize(const float* __restrict__ gamma, const float* __restrict__ beta) {
    int t = threadIdx.x;
    float mean = g_stats[t] / NTOT;
    float var  = g_stats[256 + t] / NTOT - mean*mean;
    float rstd = rsqrtf(var + 1e-5f);
    float sc = gamma[t] * rstd;
    g_scale[t] = sc;
    g_shift[t] = beta[t] - mean*sc;
}

// ---------------- affine + NHWC -> NCHW ----------------
__global__ void k_norm(float* __restrict__ out) {
    __shared__ float tile[32][33];
    int n  = blockIdx.z;
    int o0 = blockIdx.y * 32;
    int p0 = blockIdx.x * 32;
    int tx = threadIdx.x, ty = threadIdx.y;
#pragma unroll
    for (int i = 0; i < 4; i++) {
        int pl = ty + i*8;
        int oo = o0 + tx;
        tile[pl][tx] = g_y[((size_t)n*NP + p0 + pl)*CC + oo] * g_scale[oo] + g_shift[oo];
    }
    __syncthreads();
#pragma unroll
    for (int i = 0; i < 4; i++) {
        int ol = ty + i*8;
        out[((size_t)(n*CC + o0 + ol))*NP + p0 + tx] = tile[tx][ol];
    }
}

// ---------------- launch ----------------
extern "C" void kernel_launch(void* const* d_in, const int* in_sizes, int n_in,
                              void* d_out, int out_size) {
    const float* x     = (const float*)d_in[0];
    const float* wcat  = (const float*)d_in[1];
    const float* wscl  = (const float*)d_in[2];
    const float* gamma = (const float*)d_in[3];
    const float* beta  = (const float*)d_in[4];
    float* out = (float*)d_out;

    cudaFuncSetAttribute(k_gemm, cudaFuncAttributeMaxDynamicSharedMemorySize, SM_TOTAL);

    k_init<<<1200, 256>>>();
    {
        dim3 g(3, 96, NB*8), b(32, 8);
        k_pad_split<<<g, b>>>(x);
    }
    k_wsplit<<<(NOUT*CC)/256, 256>>>(wscl, wcat);
    {
        dim3 g(NP/128, NOUT/128, NB);
        k_gemm<<<g, 256, SM_TOTAL>>>();
    }
    k_gsum<<<(NB*NP*48 + 255)/256, 256>>>();
    k_softmax<<<(NB*NP*5 + 255)/256, 256>>>();
    k_gather<<<(NB*NP)/8, 256>>>();
    k_stats<<<1024, 256>>>();
    k_finalize<<<1, 256>>>(gamma, beta);
    {
        dim3 g(NP/32, CC/32, NB), b(32, 8);
        k_norm<<<g, b>>>(out);
    }
}

// round 7
// speedup vs baseline: 2.5170x; 1.0068x over previous
#include <cuda_runtime.h>
#include <cuda_bf16.h>
#include <cstdint>

#define HH 96
#define WW 96
#define CC 256
#define NP (HH*WW)          // 9216 pixels per image
#define NB 2
#define HP 98
#define PADP (HP*HP)        // 9604 padded pixels
#define NOUT 2048           // GEMM N: 1536 (Z) + 432 (guidance taps) + 80 pad
#define NGUID 1536
#define NTOT 18432.0f

// ---------------- static scratch ----------------
__device__ __nv_bfloat16 g_Ahi[(size_t)NB*PADP*CC];   // padded NHWC x, hi bf16
__device__ __nv_bfloat16 g_Alo[(size_t)NB*PADP*CC];   // residual lo bf16
__device__ __nv_bfloat16 g_Bhi[(size_t)NOUT*CC];      // [W_t ; tap weights] hi
__device__ __nv_bfloat16 g_Blo[(size_t)NOUT*CC];      // lo
__device__ float g_Z[(size_t)NB*NP*NOUT];             // GEMM output (Z + tap partials)
__device__ float g_w[(size_t)NB*NP*48];               // guidance -> softmax weights
__device__ float g_y[(size_t)NB*NP*CC];               // pre-BN output, NHWC
__device__ float g_stats[512];
__device__ float g_scale[CC];
__device__ float g_shift[CC];

// ================= helpers =================
__device__ __forceinline__ uint32_t smem_u32(const void* p) {
    uint32_t a;
    asm("{ .reg .u64 t; cvta.to.shared.u64 t, %1; cvt.u32.u64 %0, t; }" : "=r"(a) : "l"(p));
    return a;
}
#define SWZ128(o) ((o) ^ (((o) >> 3) & 0x70))

__device__ __forceinline__ void ldsm_x4(uint32_t& r0, uint32_t& r1, uint32_t& r2, uint32_t& r3,
                                        uint32_t addr) {
    asm volatile("ldmatrix.sync.aligned.m8n8.x4.shared.b16 {%0,%1,%2,%3}, [%4];"
                 : "=r"(r0), "=r"(r1), "=r"(r2), "=r"(r3) : "r"(addr));
}
__device__ __forceinline__ void mma16816(float* d, const uint32_t* a, const uint32_t* b) {
    asm volatile("mma.sync.aligned.m16n8k16.row.col.f32.bf16.bf16.f32 "
                 "{%0,%1,%2,%3}, {%4,%5,%6,%7}, {%8,%9}, {%0,%1,%2,%3};"
                 : "+f"(d[0]), "+f"(d[1]), "+f"(d[2]), "+f"(d[3])
                 : "r"(a[0]), "r"(a[1]), "r"(a[2]), "r"(a[3]), "r"(b[0]), "r"(b[1]));
}
__device__ __forceinline__ void cpasync16(uint32_t dst, const void* src) {
    asm volatile("cp.async.cg.shared.global [%0], [%1], 16;" :: "r"(dst), "l"(src));
}
#define CP_COMMIT() asm volatile("cp.async.commit_group;" ::: "memory")
#define CP_WAIT(n)  asm volatile("cp.async.wait_group %0;" :: "n"(n) : "memory")

// ---------------- init: zero bf16 padded inputs + stats ----------------
__global__ void k_init() {
    size_t total = ((size_t)NB*PADP*CC) / 8;   // uint4 = 8 bf16
    size_t stride = (size_t)gridDim.x * blockDim.x;
    uint4 z = make_uint4(0, 0, 0, 0);
    for (size_t i = (size_t)blockIdx.x*blockDim.x + threadIdx.x; i < total; i += stride) {
        ((uint4*)g_Ahi)[i] = z;
        ((uint4*)g_Alo)[i] = z;
    }
    size_t t0 = (size_t)blockIdx.x*blockDim.x + threadIdx.x;
    if (t0 < 512) g_stats[t0] = 0.f;
}

// ---------------- NCHW -> padded NHWC, split fp32 -> bf16 hi/lo ----------------
__global__ void k_pad_split(const float* __restrict__ x) {
    __shared__ float tile[32][33];
    int n  = blockIdx.z >> 3;
    int c0 = (blockIdx.z & 7) * 32;
    int y  = blockIdx.y;
    int x0 = blockIdx.x * 32;
    int tx = threadIdx.x, ty = threadIdx.y;
#pragma unroll
    for (int i = 0; i < 4; i++) {
        int c = c0 + ty + i*8;
        tile[ty + i*8][tx] = x[(((size_t)n*CC + c)*HH + y)*WW + x0 + tx];
    }
    __syncthreads();
#pragma unroll
    for (int i = 0; i < 4; i++) {
        int xl = ty + i*8;
        int c  = c0 + tx;
        float v = tile[tx][xl];
        __nv_bfloat16 h = __float2bfloat16(v);
        float lo = v - __bfloat162float(h);
        size_t idx = ((size_t)n*PADP + (size_t)(y+1)*HP + (x0 + xl + 1))*CC + c;
        g_Ahi[idx] = h;
        g_Alo[idx] = __float2bfloat16(lo);
    }
}

// ---------------- build B = [W_t ; tap weights], split hi/lo ----------------
__global__ void k_wsplit(const float* __restrict__ ws, const float* __restrict__ wcat) {
    int i = blockIdx.x*256 + threadIdx.x;   // over NOUT*CC
    int mp = i >> 8, c = i & 255;
    float v = 0.f;
    if (mp < NGUID) {
        int o = mp & 255, j = mp >> 8;
        v = ws[(size_t)o*NGUID + j*256 + c];
    } else if (mp < NGUID + 432) {
        int t = mp - NGUID, tap = t / 48, oc = t % 48;
        if (oc < 45) v = wcat[((size_t)(oc*256 + c))*9 + tap];
    }
    __nv_bfloat16 h = __float2bfloat16(v);
    g_Bhi[i] = h;
    g_Blo[i] = __float2bfloat16(v - __bfloat162float(h));
}

// ---------------- warp-MMA GEMM, cp.async double-buffered ----------------
// Stage layout (64 KB): AHI 16K | ALO 16K | BHI 16K | BLO 16K. Two stages = 128 KB.
#define SM_AHI 0
#define SM_ALO 16384
#define SM_BHI 32768
#define SM_BLO 49152
#define STAGE_SZ 65536
#define SM_TOTAL (2*STAGE_SZ)

__global__ __launch_bounds__(256, 1) void k_gemm() {
    extern __shared__ char smem[];
    uint32_t smemu = smem_u32(smem);
    int tid = threadIdx.x, wid = tid >> 5, lane = tid & 31;
    int n  = blockIdx.z;
    int pb = blockIdx.x * 128;
    int nb = blockIdx.y * 128;

    // ---- loader mapping: thread -> (row r, half); 4x16B per array per chunk ----
    int r = tid >> 1;
    int half = tid & 1;
    int p  = pb + r;
    int py = p / WW, px = p % WW;
    size_t aoff = ((size_t)n*PADP + (size_t)(py+1)*HP + (px+1))*CC + half*32;
    size_t boff = (size_t)(nb + r)*CC + half*32;
    uint32_t so[4];
#pragma unroll
    for (int i = 0; i < 4; i++) {
        uint32_t o = (uint32_t)(r*128 + half*64 + i*16);
        so[i] = SWZ128(o);
    }

    // ---- warp tile mapping: 4 warps over M (32 each), 2 over N (64 each) ----
    int wm = wid & 3, wn = wid >> 2;

    uint32_t xorv = (uint32_t)((lane & 7) << 4);
    int a_row0 = wm*32 + ((lane >> 3) & 1)*8 + (lane & 7);
    uint32_t a_colsel = (uint32_t)((lane >> 4) * 16);
    int b_row0 = wn*64 + ((lane >> 4))*8 + (lane & 7);
    uint32_t b_colsel = (uint32_t)(((lane >> 3) & 1) * 16);

    uint32_t aHi0 = smemu + SM_AHI + (uint32_t)(a_row0*128);
    uint32_t aHi1 = aHi0 + 16*128;
    uint32_t aLo0 = aHi0 + (SM_ALO - SM_AHI);
    uint32_t aLo1 = aHi1 + (SM_ALO - SM_AHI);
    uint32_t bHi  = smemu + SM_BHI + (uint32_t)(b_row0*128);
    uint32_t bLo  = bHi + (SM_BLO - SM_BHI);

    float acc[2][8][4];
#pragma unroll
    for (int t = 0; t < 2; t++)
#pragma unroll
        for (int q = 0; q < 8; q++)
#pragma unroll
            for (int e = 0; e < 4; e++) acc[t][q][e] = 0.f;

    // ---- async loader ----
    auto issue = [&](int kc, int stage) {
        uint32_t sb = smemu + (uint32_t)stage*STAGE_SZ;
        const uint4* pah = (const uint4*)(g_Ahi + aoff + kc*64);
        const uint4* pal = (const uint4*)(g_Alo + aoff + kc*64);
        const uint4* pbh = (const uint4*)(g_Bhi + boff + kc*64);
        const uint4* pbl = (const uint4*)(g_Blo + boff + kc*64);
#pragma unroll
        for (int i = 0; i < 4; i++) {
            cpasync16(sb + SM_AHI + so[i], pah + i);
            cpasync16(sb + SM_ALO + so[i], pal + i);
            cpasync16(sb + SM_BHI + so[i], pbh + i);
            cpasync16(sb + SM_BLO + so[i], pbl + i);
        }
    };

    issue(0, 0);
    CP_COMMIT();

    for (int kc = 0; kc < 4; kc++) {
        if (kc < 3) {
            issue(kc + 1, (kc + 1) & 1);
            CP_COMMIT();
            CP_WAIT(1);
        } else {
            CP_WAIT(0);
        }
        __syncthreads();

        uint32_t soff = (uint32_t)(kc & 1) * STAGE_SZ;
#pragma unroll
        for (int ks = 0; ks < 4; ks++) {
            uint32_t aoffs = ((uint32_t)(ks*32) + a_colsel) ^ xorv;
            uint32_t boffs = ((uint32_t)(ks*32) + b_colsel) ^ xorv;

            uint32_t ah[2][4], al[2][4];
            ldsm_x4(ah[0][0], ah[0][1], ah[0][2], ah[0][3], aHi0 + soff + aoffs);
            ldsm_x4(ah[1][0], ah[1][1], ah[1][2], ah[1][3], aHi1 + soff + aoffs);
            ldsm_x4(al[0][0], al[0][1], al[0][2], al[0][3], aLo0 + soff + aoffs);
            ldsm_x4(al[1][0], al[1][1], al[1][2], al[1][3], aLo1 + soff + aoffs);

#pragma unroll
            for (int qp = 0; qp < 4; qp++) {
                uint32_t bh[4], bl[4];
                ldsm_x4(bh[0], bh[1], bh[2], bh[3], bHi + soff + (uint32_t)(qp*16*128) + boffs);
                ldsm_x4(bl[0], bl[1], bl[2], bl[3], bLo + soff + (uint32_t)(qp*16*128) + boffs);
                int q0 = qp*2, q1 = qp*2 + 1;
                mma16816(acc[0][q0], ah[0], bh + 0);
                mma16816(acc[1][q0], ah[1], bh + 0);
                mma16816(acc[0][q1], ah[0], bh + 2);
                mma16816(acc[1][q1], ah[1], bh + 2);
                mma16816(acc[0][q0], ah[0], bl + 0);
                mma16816(acc[1][q0], ah[1], bl + 0);
                mma16816(acc[0][q1], ah[0], bl + 2);
                mma16816(acc[1][q1], ah[1], bl + 2);
                mma16816(acc[0][q0], al[0], bh + 0);
                mma16816(acc[1][q0], al[1], bh + 0);
                mma16816(acc[0][q1], al[0], bh + 2);
                mma16816(acc[1][q1], al[1], bh + 2);
            }
        }
        __syncthreads();
    }

    // ---- epilogue: write fragments to g_Z ----
#pragma unroll
    for (int t = 0; t < 2; t++) {
        size_t row = (size_t)n*NP + pb + wm*32 + t*16 + (lane >> 2);
        float* zbase = g_Z + row*NOUT + nb + wn*64 + (lane & 3)*2;
#pragma unroll
        for (int q = 0; q < 8; q++) {
            *(float2*)(zbase + q*8)          = make_float2(acc[t][q][0], acc[t][q][1]);
            *(float2*)(zbase + q*8 + 8*NOUT) = make_float2(acc[t][q][2], acc[t][q][3]);
        }
    }
}

// ---------------- guidance = shifted sum of tap partials ----------------
__global__ void k_gsum() {
    int i = blockIdx.x*256 + threadIdx.x;
    if (i >= NB*NP*48) return;
    int oc = i % 48;
    int P  = i / 48;
    int n  = P / NP, p = P % NP;
    int py = p / WW, px = p % WW;
    float s = 0.f;
#pragma unroll
    for (int tap = 0; tap < 9; tap++) {
        int dy = tap/3 - 1, dx = tap%3 - 1;
        int qy = py + dy, qx = px + dx;
        if ((unsigned)qy < HH && (unsigned)qx < WW)
            s += g_Z[((size_t)n*NP + qy*WW + qx)*NOUT + NGUID + tap*48 + oc];
    }
    g_w[(size_t)P*48 + oc] = s;
}

// ---------------- softmax over each 9-channel group ----------------
__global__ void k_softmax() {
    int i = blockIdx.x*256 + threadIdx.x;
    if (i >= NB*NP*5) return;
    int br  = i % 5;
    int np_ = i / 5;
    float* row = g_w + (size_t)np_*48 + 9*br;
    float v[9], m = -1e30f;
#pragma unroll
    for (int k = 0; k < 9; k++) { v[k] = row[k]; m = fmaxf(m, v[k]); }
    float s = 0.f;
#pragma unroll
    for (int k = 0; k < 9; k++) { v[k] = __expf(v[k] - m); s += v[k]; }
    float inv = 1.f / s;
#pragma unroll
    for (int k = 0; k < 9; k++) row[k] = v[k] * inv;
}

// ---------------- gather: y = z0 + sum_br sum_k w * shift(z_br) ----------------
__global__ __launch_bounds__(256) void k_gather() {
    __shared__ float wsh[8][48];
    int warp = threadIdx.x >> 5, lane = threadIdx.x & 31;
    int P = blockIdx.x*8 + warp;
    int n = P / NP, p = P % NP;
    int py = p / WW, px = p % WW;

    const float* wrow = g_w + (size_t)P*48;
    if (lane < 45) wsh[warp][lane] = wrow[lane];
    if (lane < 13) wsh[warp][32 + lane] = wrow[32 + lane];
    __syncwarp();

    const float* z0 = g_Z + (size_t)P*NOUT + lane*8;
    float4 A0 = *(const float4*)z0;
    float4 A1 = *(const float4*)(z0 + 4);

    const int DS[5] = {1, 6, 12, 24, 36};
#pragma unroll
    for (int br = 0; br < 5; ++br) {
        int d = DS[br];
#pragma unroll
        for (int k = 0; k < 9; k++) {
            int dy = (k/3 - 1)*d, dx = (k%3 - 1)*d;
            int ny = py + dy, nx = px + dx;
            if ((unsigned)ny < HH && (unsigned)nx < WW) {
                float w = wsh[warp][br*9 + k];
                const float* zr = g_Z + ((size_t)n*NP + ny*WW + nx)*NOUT + (br+1)*256 + lane*8;
                float4 v0 = *(const float4*)zr;
                float4 v1 = *(const float4*)(zr + 4);
                A0.x += w*v0.x; A0.y += w*v0.y; A0.z += w*v0.z; A0.w += w*v0.w;
                A1.x += w*v1.x; A1.y += w*v1.y; A1.z += w*v1.z; A1.w += w*v1.w;
            }
        }
    }
    float* yr = g_y + (size_t)P*CC + lane*8;
    *(float4*)yr       = A0;
    *((float4*)yr + 1) = A1;
}

// ---------------- BN stats ----------------
__global__ void k_stats() {
    int t = threadIdx.x;
    size_t row0 = (size_t)blockIdx.x * 18;
    float s = 0.f, s2 = 0.f;
    for (int r = 0; r < 18; r++) {
        float v = g_y[(row0 + r)*CC + t];
        s += v; s2 += v*v;
    }
    atomicAdd(&g_stats[t], s);
    atomicAdd(&g_stats[256 + t], s2);
}

__global__ void k_finalize(const float* __restrict__ gamma, const float* __restrict__ beta) {
    int t = threadIdx.x;
    float mean = g_stats[t] / NTOT;
    float var  = g_stats[256 + t] / NTOT - mean*mean;
    float rstd = rsqrtf(var + 1e-5f);
    float sc = gamma[t] * rstd;
    g_scale[t] = sc;
    g_shift[t] = beta[t] - mean*sc;
}

// ---------------- affine + NHWC -> NCHW ----------------
__global__ void k_norm(float* __restrict__ out) {
    __shared__ float tile[32][33];
    int n  = blockIdx.z;
    int o0 = blockIdx.y * 32;
    int p0 = blockIdx.x * 32;
    int tx = threadIdx.x, ty = threadIdx.y;
#pragma unroll
    for (int i = 0; i < 4; i++) {
        int pl = ty + i*8;
        int oo = o0 + tx;
        tile[pl][tx] = g_y[((size_t)n*NP + p0 + pl)*CC + oo] * g_scale[oo] + g_shift[oo];
    }
    __syncthreads();
#pragma unroll
    for (int i = 0; i < 4; i++) {
        int ol = ty + i*8;
        out[((size_t)(n*CC + o0 + ol))*NP + p0 + tx] = tile[tx][ol];
    }
}

// ---------------- launch ----------------
extern "C" void kernel_launch(void* const* d_in, const int* in_sizes, int n_in,
                              void* d_out, int out_size) {
    const float* x     = (const float*)d_in[0];
    const float* wcat  = (const float*)d_in[1];
    const float* wscl  = (const float*)d_in[2];
    const float* gamma = (const float*)d_in[3];
    const float* beta  = (const float*)d_in[4];
    float* out = (float*)d_out;

    cudaFuncSetAttribute(k_gemm, cudaFuncAttributeMaxDynamicSharedMemorySize, SM_TOTAL);

    k_init<<<1200, 256>>>();
    {
        dim3 g(3, 96, NB*8), b(32, 8);
        k_pad_split<<<g, b>>>(x);
    }
    k_wsplit<<<(NOUT*CC)/256, 256>>>(wscl, wcat);
    {
        dim3 g(NP/128, NOUT/128, NB);
        k_gemm<<<g, 256, SM_TOTAL>>>();
    }
    k_gsum<<<(NB*NP*48 + 255)/256, 256>>>();
    k_softmax<<<(NB*NP*5 + 255)/256, 256>>>();
    k_gather<<<(NB*NP)/8, 256>>>();
    k_stats<<<1024, 256>>>();
    k_finalize<<<1, 256>>>(gamma, beta);
    {
        dim3 g(NP/32, CC/32, NB), b(32, 8);
        k_norm<<<g, b>>>(out);
    }
}